// round 14
// baseline (speedup 1.0000x reference)
#include <cuda_runtime.h>
#include <cuda_fp16.h>
#include <cstdint>

// Problem constants
#define NB 8      // batch
#define NC 64     // channels
#define NN 4096   // H*W
#define ND 8      // qk head dim (exact, no padding: m16n8k8)
#define TQ 64     // queries per CTA (4 warps x 16 rows)
#define TK 64     // keys per tile (halved: smem 19.5KB -> 6 CTAs/SM resident)
#define THREADS 128
#define SPLIT 2
#define NT (NN / TK / SPLIT)   // 32 key tiles per CTA

#define LOG2E 1.4426950408889634f

// Scratch (__device__ globals; no allocation allowed)
__device__ __align__(16) __half g_q[NB * NN * ND];
__device__ __align__(16) __half g_k[NB * NN * ND];
__device__ __align__(16) __half g_v[NB * NN * NC];
// split-K partials (fp16 O: errors damped ~1000x by the +x residual)
__device__ __align__(16) __half g_O[SPLIT][NB * NC * NN];
__device__ __align__(16) float  g_l[SPLIT][NB * NN];

// ---------------------------------------------------------------------------
// Inline PTX
// ---------------------------------------------------------------------------
__device__ __forceinline__ uint32_t smem_u32(const void* p) {
    uint32_t a;
    asm("{ .reg .u64 t; cvta.to.shared.u64 t, %1; cvt.u32.u64 %0, t; }"
        : "=r"(a) : "l"(p));
    return a;
}

#define LDMATRIX_X2(r0, r1, addr) \
    asm volatile("ldmatrix.sync.aligned.m8n8.x2.shared.b16 {%0,%1}, [%2];" \
                 : "=r"(r0), "=r"(r1) : "r"(addr))

#define LDMATRIX_X4(r0, r1, r2, r3, addr) \
    asm volatile("ldmatrix.sync.aligned.m8n8.x4.shared.b16 {%0,%1,%2,%3}, [%4];" \
                 : "=r"(r0), "=r"(r1), "=r"(r2), "=r"(r3) : "r"(addr))

#define LDMATRIX_X4_T(r0, r1, r2, r3, addr) \
    asm volatile("ldmatrix.sync.aligned.m8n8.x4.trans.shared.b16 {%0,%1,%2,%3}, [%4];" \
                 : "=r"(r0), "=r"(r1), "=r"(r2), "=r"(r3) : "r"(addr))

// S = q.k, K=8, f16 accum; C-fragment == PV A-fragment k-slots (FA2 reuse)
#define MMA_K8_S_F16(d0, d1, a0, a1, b0) \
    asm volatile("mma.sync.aligned.m16n8k8.row.col.f16.f16.f16.f16 " \
                 "{%0,%1}, {%2,%3}, {%4}, {%5,%6};" \
                 : "=r"(d0), "=r"(d1) \
                 : "r"(a0), "r"(a1), "r"(b0), "r"(0u), "r"(0u))

// k16 MMA, f16 accumulate in-place
#define MMA_16816_PV_F16(d0, d1, a0, a1, a2, a3, b0, b1) \
    asm volatile("mma.sync.aligned.m16n8k16.row.col.f16.f16.f16.f16 " \
                 "{%0,%1}, {%2,%3,%4,%5}, {%6,%7}, {%0,%1};" \
                 : "+r"(d0), "+r"(d1) \
                 : "r"(a0), "r"(a1), "r"(a2), "r"(a3), "r"(b0), "r"(b1))

#define EX2_F16X2(d, a) \
    asm("ex2.approx.f16x2 %0, %1;" : "=r"(d) : "r"(a))
#define HADD2(d, a, b) \
    asm("add.rn.f16x2 %0, %1, %2;" : "=r"(d) : "r"(a), "r"(b))

#define CP_ASYNC16(smem_addr, gptr) \
    asm volatile("cp.async.cg.shared.global [%0], [%1], 16;" \
                 :: "r"(smem_addr), "l"(gptr) : "memory")
#define CP_COMMIT() asm volatile("cp.async.commit_group;" ::: "memory")
#define CP_WAIT(n)  asm volatile("cp.async.wait_group %0;" :: "n"(n) : "memory")

// SMEM layout for attn (static, double-buffered K/V; TK=64)
#define SM_Q   0                    // 64 x 16B   (1KB)
#define SM_K0  1024                 // 64 x 16B   (1KB)
#define SM_K1  2048
#define SM_V0  3072                 // 64 x 128B  (8KB)
#define SM_V1  11264
#define SM_BYTES 19456              // epilogue reuses [0,16KB) as O stage

// ============================================================================
// Proj tile compute (verified rounds 10-13): A = x^T fragments from swizzled
// s_x tile, B = W rows, f16-accum MMAs with bias preloaded.
// ============================================================================
__device__ __forceinline__ void proj_compute_tile(
    uint32_t sx, uint32_t sv, uint32_t sq, uint32_t sk,
    const float* s_bv, const float* s_bq, const float* s_bk,
    int b, int n0, int tid) {
    int wm = tid >> 5, l = tid & 31;
    int mat = l >> 3, j = l & 7;
    int cpr = l & 3, r = l >> 2;
    uint32_t xorj = (uint32_t)(j << 4);

    // A fragments: 4 k-chunks of 16 ch (m = this warp's 16 positions)
    uint32_t a[4][4];
#pragma unroll
    for (int kc = 0; kc < 4; kc++) {
        uint32_t row = (uint32_t)(kc * 16 + ((mat >> 1) << 3) + j);
        uint32_t posb = (uint32_t)((wm << 5) + ((mat & 1) << 4));
        LDMATRIX_X4_T(a[kc][0], a[kc][1], a[kc][2], a[kc][3],
                      sx + row * 128 + (posb ^ xorj));
    }

    // accumulators preloaded with bias
    uint32_t vacc[8][2];
#pragma unroll
    for (int nb = 0; nb < 8; nb++) {
        __half2 hb = __floats2half2_rn(s_bv[nb * 8 + 2 * cpr], s_bv[nb * 8 + 2 * cpr + 1]);
        vacc[nb][0] = vacc[nb][1] = *reinterpret_cast<uint32_t*>(&hb);
    }
    uint32_t qacc[2], kacc[2];
    {
        __half2 hq = __floats2half2_rn(s_bq[2 * cpr], s_bq[2 * cpr + 1]);
        __half2 hk = __floats2half2_rn(s_bk[2 * cpr], s_bk[2 * cpr + 1]);
        qacc[0] = qacc[1] = *reinterpret_cast<uint32_t*>(&hq);
        kacc[0] = kacc[1] = *reinterpret_cast<uint32_t*>(&hk);
    }

    // v GEMM
#pragma unroll
    for (int nbp = 0; nbp < 4; nbp++) {
#pragma unroll
        for (int kc = 0; kc < 4; kc++) {
            uint32_t row = (uint32_t)(nbp * 16 + ((mat >> 1) << 3) + j);
            uint32_t chb = (uint32_t)((kc << 5) + ((mat & 1) << 4));
            uint32_t w0, w1, w2, w3;
            LDMATRIX_X4(w0, w1, w2, w3, sv + row * 128 + (chb ^ xorj));
            MMA_16816_PV_F16(vacc[2 * nbp][0], vacc[2 * nbp][1],
                             a[kc][0], a[kc][1], a[kc][2], a[kc][3], w0, w1);
            MMA_16816_PV_F16(vacc[2 * nbp + 1][0], vacc[2 * nbp + 1][1],
                             a[kc][0], a[kc][1], a[kc][2], a[kc][3], w2, w3);
        }
    }
    // q/k GEMMs
#pragma unroll
    for (int kc2 = 0; kc2 < 2; kc2++) {
        uint32_t chb = (uint32_t)((kc2 << 6) + ((mat >> 1) << 5) + ((mat & 1) << 4));
        uint32_t addr_off = (uint32_t)(j * 128) + (chb ^ xorj);
        uint32_t q0, q1, q2, q3;
        LDMATRIX_X4(q0, q1, q2, q3, sq + addr_off);
        MMA_16816_PV_F16(qacc[0], qacc[1],
                         a[2 * kc2][0], a[2 * kc2][1], a[2 * kc2][2], a[2 * kc2][3], q0, q1);
        MMA_16816_PV_F16(qacc[0], qacc[1],
                         a[2 * kc2 + 1][0], a[2 * kc2 + 1][1], a[2 * kc2 + 1][2], a[2 * kc2 + 1][3], q2, q3);
        uint32_t k0, k1, k2, k3;
        LDMATRIX_X4(k0, k1, k2, k3, sk + addr_off);
        MMA_16816_PV_F16(kacc[0], kacc[1],
                         a[2 * kc2][0], a[2 * kc2][1], a[2 * kc2][2], a[2 * kc2][3], k0, k1);
        MMA_16816_PV_F16(kacc[0], kacc[1],
                         a[2 * kc2 + 1][0], a[2 * kc2 + 1][1], a[2 * kc2 + 1][2], a[2 * kc2 + 1][3], k2, k3);
    }

    // epilogue: direct half2 stores in the attn-consumable layouts
    int pos0 = wm * 16 + r;
    int pos1 = pos0 + 8;
    size_t nidx0 = (size_t)b * NN + n0 + pos0;
    size_t nidx1 = (size_t)b * NN + n0 + pos1;
    int sw0 = (pos0 & 7) << 3, sw1 = (pos1 & 7) << 3;
    __half* vo0 = g_v + nidx0 * NC;
    __half* vo1 = g_v + nidx1 * NC;
#pragma unroll
    for (int nb = 0; nb < 8; nb++) {
        int ch = nb * 8 + 2 * cpr;
        *reinterpret_cast<uint32_t*>(vo0 + (ch ^ sw0)) = vacc[nb][0];
        *reinterpret_cast<uint32_t*>(vo1 + (ch ^ sw1)) = vacc[nb][1];
    }
    *reinterpret_cast<uint32_t*>(g_q + nidx0 * ND + 2 * cpr) = qacc[0];
    *reinterpret_cast<uint32_t*>(g_q + nidx1 * ND + 2 * cpr) = qacc[1];
    *reinterpret_cast<uint32_t*>(g_k + nidx0 * ND + 2 * cpr) = kacc[0];
    *reinterpret_cast<uint32_t*>(g_k + nidx1 * ND + 2 * cpr) = kacc[1];
}

// ============================================================================
// Kernel 1: projections, cp.async x staging.
//   x tile lands in smem raw (fp32) via cp.async — no LDG->cvt->STS register
//   chains, full MLP — its latency overlaps the W-stage LDGs. Then each
//   thread converts its OWN cp.async'd bytes (per-thread wait_group makes
//   this sync-free) into the swizzled fp16 tile, syncs, and runs the GEMM.
// ============================================================================
__global__ __launch_bounds__(THREADS) void proj_kernel(
    const float* __restrict__ x,
    const float* __restrict__ wq, const float* __restrict__ bq,
    const float* __restrict__ wk, const float* __restrict__ bk,
    const float* __restrict__ wv, const float* __restrict__ bv) {
    __shared__ __align__(16) float  s_xraw[64 * 64];   // 16KB raw fp32 x tile
    __shared__ __align__(16) __half s_x[64 * 64];      // 8KB swizzled fp16
    __shared__ __align__(16) __half s_wv[64 * 64];
    __shared__ __align__(16) __half s_wq[8 * 64];
    __shared__ __align__(16) __half s_wk[8 * 64];
    __shared__ float s_bv[64], s_bq[8], s_bk[8];

    int tid = threadIdx.x;
    int b = blockIdx.x >> 6;                 // 64 tiles of 64 pos per batch
    int n0 = (blockIdx.x & 63) * 64;
    char* sxc = reinterpret_cast<char*>(s_x);
    char* svc = reinterpret_cast<char*>(s_wv);
    char* sqc = reinterpret_cast<char*>(s_wq);
    char* skc = reinterpret_cast<char*>(s_wk);

    // ---- cp.async the raw x tile [64 ch x 64 pos] fp32 ----
    const float4* x4p = reinterpret_cast<const float4*>(x + (size_t)b * NC * NN + n0);
    uint32_t sxr = smem_u32(s_xraw);
    for (int t = tid; t < 1024; t += THREADS) {
        const float4* src = x4p + (size_t)(t >> 4) * (NN / 4) + (t & 15);
        CP_ASYNC16(sxr + (uint32_t)t * 16, src);
    }
    CP_COMMIT();

    // ---- stage W while the x tile is in flight ----
    const float4* wv4 = reinterpret_cast<const float4*>(wv);
    for (int t = tid; t < 1024; t += THREADS) {
        int r = t >> 4, c4 = t & 15;
        float4 w = wv4[t];
        uint32_t off = (uint32_t)(r * 128 + ((8 * c4) ^ ((r & 7) << 4)));
        *reinterpret_cast<__half2*>(svc + off)     = __floats2half2_rn(w.x, w.y);
        *reinterpret_cast<__half2*>(svc + off + 4) = __floats2half2_rn(w.z, w.w);
    }
    const float4* wq4 = reinterpret_cast<const float4*>(wq);
    const float4* wk4 = reinterpret_cast<const float4*>(wk);
    for (int t = tid; t < 128; t += THREADS) {
        int r = t >> 4, c4 = t & 15;
        uint32_t off = (uint32_t)(r * 128 + ((8 * c4) ^ ((r & 7) << 4)));
        float4 a = wq4[t];
        *reinterpret_cast<__half2*>(sqc + off)     = __floats2half2_rn(a.x * LOG2E, a.y * LOG2E);
        *reinterpret_cast<__half2*>(sqc + off + 4) = __floats2half2_rn(a.z * LOG2E, a.w * LOG2E);
        float4 k = wk4[t];
        *reinterpret_cast<__half2*>(skc + off)     = __floats2half2_rn(k.x, k.y);
        *reinterpret_cast<__half2*>(skc + off + 4) = __floats2half2_rn(k.z, k.w);
    }
    if (tid < 64) s_bv[tid] = bv[tid];
    if (tid < 8) { s_bq[tid] = bq[tid] * LOG2E; s_bk[tid] = bk[tid]; }

    // ---- convert own cp.async bytes -> swizzled fp16 (no sync needed) ----
    CP_WAIT(0);
    const float4* xr4 = reinterpret_cast<const float4*>(s_xraw);
    for (int t = tid; t < 1024; t += THREADS) {
        float4 w = xr4[t];
        int c = t >> 4, p4 = t & 15;
        uint32_t off = (uint32_t)(c * 128 + ((8 * p4) ^ ((c & 7) << 4)));
        *reinterpret_cast<__half2*>(sxc + off)     = __floats2half2_rn(w.x, w.y);
        *reinterpret_cast<__half2*>(sxc + off + 4) = __floats2half2_rn(w.z, w.w);
    }
    __syncthreads();

    proj_compute_tile(smem_u32(s_x), smem_u32(s_wv), smem_u32(s_wq),
                      smem_u32(s_wk), s_bv, s_bq, s_bk, b, n0, tid);
}

// ============================================================================
// Kernel 2: flash attention partial, SPLIT=2, TK=64 (smem 19.5KB -> 6 CTAs/SM
//   = 24 resident warps). Same numerics as rounds 9-13.
// ============================================================================
__global__ __launch_bounds__(THREADS, 6) void attn_kernel() {
    __shared__ __align__(16) char smem[SM_BYTES];
    uint32_t sb = smem_u32(smem);

    int tid = threadIdx.x;
    int w = tid >> 5, l = tid & 31;
    int lr = l & 7, sub = l >> 3;
    int qr = w * 16;
    int b = blockIdx.y;
    int z = blockIdx.z;
    int i0 = blockIdx.x * TQ;
    int j_base = z * (NN / SPLIT);

    const uint4* gq4 = reinterpret_cast<const uint4*>(g_q) + (size_t)b * NN + i0;
    const uint4* gk4 = reinterpret_cast<const uint4*>(g_k) + (size_t)b * NN + j_base;
    const uint4* gv4 = reinterpret_cast<const uint4*>(g_v) + (size_t)b * NN * 8 + (size_t)j_base * 8;

    // prologue: stage Q + tile 0 (buffer 0)
    for (int t = tid; t < 64; t += THREADS)
        CP_ASYNC16(sb + SM_Q + (uint32_t)t * 16, gq4 + t);
    // K tile: 64 rows x 16B = 64 uint4 ; V tile: 64 rows x 128B = 512 uint4
    if (tid < 64)
        CP_ASYNC16(sb + SM_K0 + (uint32_t)tid * 16, gk4 + tid);
    for (int t = tid; t < 512; t += THREADS)
        CP_ASYNC16(sb + SM_V0 + (uint32_t)t * 16, gv4 + t);
    CP_COMMIT();
    CP_WAIT(0);
    __syncthreads();

    uint32_t qaddr = sb + SM_Q + (uint32_t)(qr + (l & 15)) * 16;
    uint32_t koff = (uint32_t)(l & 15) * 16;
    uint32_t voff = (uint32_t)(lr + (sub & 1) * 8) * 128;
    uint32_t kb2[2] = { sb + SM_K0 + koff, sb + SM_K1 + koff };
    uint32_t vb2[2] = { sb + SM_V0 + voff, sb + SM_V1 + voff };
    int vsub = sub >> 1;

    uint32_t qa0, qa1;
    LDMATRIX_X2(qa0, qa1, qaddr);

    float o[32];
#pragma unroll
    for (int k = 0; k < 32; k++) o[k] = 0.f;
    float lsum0 = 0.f, lsum1 = 0.f;

    for (int t = 0; t < NT; t++) {
        if (t + 1 < NT) {
            uint32_t kd = (t & 1) ? SM_K0 : SM_K1;
            uint32_t vd = (t & 1) ? SM_V0 : SM_V1;
            const uint4* gk = gk4 + (t + 1) * 64;
            const uint4* gv = gv4 + (t + 1) * 512;
            if (tid < 64)
                CP_ASYNC16(sb + kd + (uint32_t)tid * 16, gk + tid);
            for (int u = tid; u < 512; u += THREADS)
                CP_ASYNC16(sb + vd + (uint32_t)u * 16, gv + u);
            CP_COMMIT();
        }
        if (t > 0) {
            if (t + 1 < NT) CP_WAIT(1); else CP_WAIT(0);
            __syncthreads();
        }

        uint32_t kbase = kb2[t & 1];
        uint32_t vbase = vb2[t & 1];
        uint32_t acc0 = 0, acc1 = 0;
        uint32_t o16[16];
#pragma unroll
        for (int k = 0; k < 16; k++) o16[k] = 0;

#pragma unroll
        for (int jt = 0; jt < 4; jt++) {           // 16 keys per step, 64/tile
            uint32_t kr0, kr1;
            LDMATRIX_X2(kr0, kr1, kbase + (uint32_t)jt * 256);

            uint32_t pa0, pa1, pa2, pa3;
            MMA_K8_S_F16(pa0, pa1, qa0, qa1, kr0);
            MMA_K8_S_F16(pa2, pa3, qa0, qa1, kr1);

            EX2_F16X2(pa0, pa0);
            EX2_F16X2(pa1, pa1);
            EX2_F16X2(pa2, pa2);
            EX2_F16X2(pa3, pa3);
            uint32_t h0, h1;
            HADD2(h0, pa0, pa2); HADD2(acc0, acc0, h0);
            HADD2(h1, pa1, pa3); HADD2(acc1, acc1, h1);

            uint32_t vrow = vbase + (uint32_t)jt * 2048;
#pragma unroll
            for (int ct = 0; ct < 8; ct += 2) {
                uint32_t vr0, vr1, vr2, vr3;
                uint32_t va = vrow + (uint32_t)(((ct + vsub) ^ lr) << 4);
                LDMATRIX_X4_T(vr0, vr1, vr2, vr3, va);
                MMA_16816_PV_F16(o16[ct * 2 + 0], o16[ct * 2 + 1],
                                 pa0, pa1, pa2, pa3, vr0, vr1);
                MMA_16816_PV_F16(o16[ct * 2 + 2], o16[ct * 2 + 3],
                                 pa0, pa1, pa2, pa3, vr2, vr3);
            }
        }

        // flush tile: f16x2 -> f32 accumulators
#pragma unroll
        for (int ct = 0; ct < 8; ct++) {
            float2 f0 = __half22float2(*reinterpret_cast<__half2*>(&o16[ct * 2]));
            float2 f1 = __half22float2(*reinterpret_cast<__half2*>(&o16[ct * 2 + 1]));
            o[ct * 4 + 0] += f0.x;
            o[ct * 4 + 1] += f0.y;
            o[ct * 4 + 2] += f1.x;
            o[ct * 4 + 3] += f1.y;
        }
        {
            float2 f0 = __half22float2(*reinterpret_cast<__half2*>(&acc0));
            float2 f1 = __half22float2(*reinterpret_cast<__half2*>(&acc1));
            lsum0 += f0.x + f0.y;
            lsum1 += f1.x + f1.y;
        }
        __syncthreads();
    }

    lsum0 += __shfl_xor_sync(0xffffffffu, lsum0, 1);
    lsum0 += __shfl_xor_sync(0xffffffffu, lsum0, 2);
    lsum1 += __shfl_xor_sync(0xffffffffu, lsum1, 1);
    lsum1 += __shfl_xor_sync(0xffffffffu, lsum1, 2);
    float* lp = g_l[z] + (size_t)b * NN + i0;
    if ((l & 3) == 0) {
        lp[qr + (l >> 2)]     = lsum0;
        lp[qr + (l >> 2) + 8] = lsum1;
    }

    __syncthreads();
    float* so = reinterpret_cast<float*>(smem);
    int row0 = qr + (l >> 2);
    int cb = (l & 3) * 2;
#pragma unroll
    for (int ct = 0; ct < 8; ct++) {
        int c0 = ct * 8 + cb;
        so[c0 * 64 + row0]           = o[ct * 4 + 0];
        so[(c0 + 1) * 64 + row0]     = o[ct * 4 + 1];
        so[c0 * 64 + row0 + 8]       = o[ct * 4 + 2];
        so[(c0 + 1) * 64 + row0 + 8] = o[ct * 4 + 3];
    }
    __syncthreads();

    __half* gO = g_O[z] + (size_t)b * NC * NN + i0;
    const float4* so4 = reinterpret_cast<const float4*>(so);
    for (int t = tid; t < 1024; t += THREADS) {
        int c = t >> 4;
        int i = (t & 15) * 4;
        float4 v = so4[t];
        __half2 h0 = __floats2half2_rn(v.x, v.y);
        __half2 h1 = __floats2half2_rn(v.z, v.w);
        uint2 pk = make_uint2(*reinterpret_cast<uint32_t*>(&h0),
                              *reinterpret_cast<uint32_t*>(&h1));
        *reinterpret_cast<uint2*>(gO + (size_t)c * NN + i) = pk;
    }
}

// ============================================================================
// Kernel 3: combine split-K partials: out = gamma*(O0+O1)/(l0+l1) + x
// ============================================================================
__global__ __launch_bounds__(256) void combine_kernel(
    const float* __restrict__ x,
    const float* __restrict__ gamma,
    float* __restrict__ out) {
    int t = blockIdx.x * 256 + threadIdx.x;
    int b = t >> 16;
    int rem = t & 65535;
    int c = rem >> 10;
    int i = (rem & 1023) << 2;
    size_t oidx = ((size_t)b * NC + c) * NN + i;
    size_t lidx = (size_t)b * NN + i;

    const __half2* p0 = reinterpret_cast<const __half2*>(&g_O[0][oidx]);
    const __half2* p1 = reinterpret_cast<const __half2*>(&g_O[1][oidx]);
    float2 a0 = __half22float2(p0[0]), a1 = __half22float2(p0[1]);
    float2 b0 = __half22float2(p1[0]), b1 = __half22float2(p1[1]);
    float4 l0 = *reinterpret_cast<const float4*>(&g_l[0][lidx]);
    float4 l1 = *reinterpret_cast<const float4*>(&g_l[1][lidx]);
    float4 xr = *reinterpret_cast<const float4*>(&x[oidx]);
    float g = __ldg(gamma);

    float4 r;
    r.x = g * (a0.x + b0.x) / (l0.x + l1.x) + xr.x;
    r.y = g * (a0.y + b0.y) / (l0.y + l1.y) + xr.y;
    r.z = g * (a1.x + b1.x) / (l0.z + l1.z) + xr.z;
    r.w = g * (a1.y + b1.y) / (l0.w + l1.w) + xr.w;
    *reinterpret_cast<float4*>(&out[oidx]) = r;
}

extern "C" void kernel_launch(void* const* d_in, const int* in_sizes, int n_in,
                              void* d_out, int out_size) {
    const float* x     = (const float*)d_in[0];
    const float* wq    = (const float*)d_in[1];
    const float* bq    = (const float*)d_in[2];
    const float* wk    = (const float*)d_in[3];
    const float* bk    = (const float*)d_in[4];
    const float* wv    = (const float*)d_in[5];
    const float* bv    = (const float*)d_in[6];
    const float* gamma = (const float*)d_in[7];
    float* out = (float*)d_out;

    proj_kernel<<<NB * NN / 64, THREADS>>>(x, wq, bq, wk, bk, wv, bv);
    attn_kernel<<<dim3(NN / TQ, NB, SPLIT), THREADS>>>();
    combine_kernel<<<NB * NC * NN / 4 / 256, 256>>>(x, gamma, out);
}

// round 15
// speedup vs baseline: 1.1472x; 1.1472x over previous
#include <cuda_runtime.h>
#include <cuda_fp16.h>
#include <cstdint>

// Problem constants
#define NB 8      // batch
#define NC 64     // channels
#define NN 4096   // H*W
#define ND 8      // qk head dim (exact, no padding: m16n8k8)
#define TQ 64     // queries per CTA (4 warps x 16 rows)
#define TK 128    // keys per tile (TK=64 experiment regressed; reverted)
#define THREADS 128
#define SPLIT 2
#define NT (NN / TK / SPLIT)   // 16 key tiles per CTA

#define LOG2E 1.4426950408889634f

// Scratch (__device__ globals; no allocation allowed)
__device__ __align__(16) __half g_q[NB * NN * ND];
__device__ __align__(16) __half g_k[NB * NN * ND];
__device__ __align__(16) __half g_v[NB * NN * NC];
// split-K partials (fp16 O: errors damped ~1000x by the +x residual)
__device__ __align__(16) __half g_O[SPLIT][NB * NC * NN];
__device__ __align__(16) float  g_l[SPLIT][NB * NN];

// ---------------------------------------------------------------------------
// Inline PTX
// ---------------------------------------------------------------------------
__device__ __forceinline__ uint32_t smem_u32(const void* p) {
    uint32_t a;
    asm("{ .reg .u64 t; cvta.to.shared.u64 t, %1; cvt.u32.u64 %0, t; }"
        : "=r"(a) : "l"(p));
    return a;
}

#define LDMATRIX_X2(r0, r1, addr) \
    asm volatile("ldmatrix.sync.aligned.m8n8.x2.shared.b16 {%0,%1}, [%2];" \
                 : "=r"(r0), "=r"(r1) : "r"(addr))

#define LDMATRIX_X4(r0, r1, r2, r3, addr) \
    asm volatile("ldmatrix.sync.aligned.m8n8.x4.shared.b16 {%0,%1,%2,%3}, [%4];" \
                 : "=r"(r0), "=r"(r1), "=r"(r2), "=r"(r3) : "r"(addr))

#define LDMATRIX_X4_T(r0, r1, r2, r3, addr) \
    asm volatile("ldmatrix.sync.aligned.m8n8.x4.trans.shared.b16 {%0,%1,%2,%3}, [%4];" \
                 : "=r"(r0), "=r"(r1), "=r"(r2), "=r"(r3) : "r"(addr))

// S = q.k, K=8, f16 accum; C-fragment == PV A-fragment k-slots (FA2 reuse)
#define MMA_K8_S_F16(d0, d1, a0, a1, b0) \
    asm volatile("mma.sync.aligned.m16n8k8.row.col.f16.f16.f16.f16 " \
                 "{%0,%1}, {%2,%3}, {%4}, {%5,%6};" \
                 : "=r"(d0), "=r"(d1) \
                 : "r"(a0), "r"(a1), "r"(b0), "r"(0u), "r"(0u))

// k16 MMA, f16 accumulate in-place
#define MMA_16816_PV_F16(d0, d1, a0, a1, a2, a3, b0, b1) \
    asm volatile("mma.sync.aligned.m16n8k16.row.col.f16.f16.f16.f16 " \
                 "{%0,%1}, {%2,%3,%4,%5}, {%6,%7}, {%0,%1};" \
                 : "+r"(d0), "+r"(d1) \
                 : "r"(a0), "r"(a1), "r"(a2), "r"(a3), "r"(b0), "r"(b1))

#define EX2_F16X2(d, a) \
    asm("ex2.approx.f16x2 %0, %1;" : "=r"(d) : "r"(a))
#define HADD2(d, a, b) \
    asm("add.rn.f16x2 %0, %1, %2;" : "=r"(d) : "r"(a), "r"(b))

#define CP_ASYNC16(smem_addr, gptr) \
    asm volatile("cp.async.cg.shared.global [%0], [%1], 16;" \
                 :: "r"(smem_addr), "l"(gptr) : "memory")
#define CP_COMMIT() asm volatile("cp.async.commit_group;" ::: "memory")
#define CP_WAIT(n)  asm volatile("cp.async.wait_group %0;" :: "n"(n) : "memory")

// SMEM layout for attn (static, double-buffered K/V; TK=128, round-13)
#define SM_Q   0                    // 64 x 16B   (1KB)
#define SM_K0  1024                 // 128 x 16B  (2KB)
#define SM_K1  3072
#define SM_V0  5120                 // 128 x 128B (16KB)
#define SM_V1  21504
#define SM_BYTES 37888              // epilogue reuses [0,16KB) as O stage

// ============================================================================
// Proj tile compute (verified rounds 10-14): A = x^T fragments from swizzled
// s_x tile, B = W rows, f16-accum MMAs with bias preloaded.
// ============================================================================
__device__ __forceinline__ void proj_compute_tile(
    uint32_t sx, uint32_t sv, uint32_t sq, uint32_t sk,
    const float* s_bv, const float* s_bq, const float* s_bk,
    int b, int n0, int tid) {
    int wm = tid >> 5, l = tid & 31;
    int mat = l >> 3, j = l & 7;
    int cpr = l & 3, r = l >> 2;
    uint32_t xorj = (uint32_t)(j << 4);

    // A fragments: 4 k-chunks of 16 ch (m = this warp's 16 positions)
    uint32_t a[4][4];
#pragma unroll
    for (int kc = 0; kc < 4; kc++) {
        uint32_t row = (uint32_t)(kc * 16 + ((mat >> 1) << 3) + j);
        uint32_t posb = (uint32_t)((wm << 5) + ((mat & 1) << 4));
        LDMATRIX_X4_T(a[kc][0], a[kc][1], a[kc][2], a[kc][3],
                      sx + row * 128 + (posb ^ xorj));
    }

    // accumulators preloaded with bias
    uint32_t vacc[8][2];
#pragma unroll
    for (int nb = 0; nb < 8; nb++) {
        __half2 hb = __floats2half2_rn(s_bv[nb * 8 + 2 * cpr], s_bv[nb * 8 + 2 * cpr + 1]);
        vacc[nb][0] = vacc[nb][1] = *reinterpret_cast<uint32_t*>(&hb);
    }
    uint32_t qacc[2], kacc[2];
    {
        __half2 hq = __floats2half2_rn(s_bq[2 * cpr], s_bq[2 * cpr + 1]);
        __half2 hk = __floats2half2_rn(s_bk[2 * cpr], s_bk[2 * cpr + 1]);
        qacc[0] = qacc[1] = *reinterpret_cast<uint32_t*>(&hq);
        kacc[0] = kacc[1] = *reinterpret_cast<uint32_t*>(&hk);
    }

    // v GEMM
#pragma unroll
    for (int nbp = 0; nbp < 4; nbp++) {
#pragma unroll
        for (int kc = 0; kc < 4; kc++) {
            uint32_t row = (uint32_t)(nbp * 16 + ((mat >> 1) << 3) + j);
            uint32_t chb = (uint32_t)((kc << 5) + ((mat & 1) << 4));
            uint32_t w0, w1, w2, w3;
            LDMATRIX_X4(w0, w1, w2, w3, sv + row * 128 + (chb ^ xorj));
            MMA_16816_PV_F16(vacc[2 * nbp][0], vacc[2 * nbp][1],
                             a[kc][0], a[kc][1], a[kc][2], a[kc][3], w0, w1);
            MMA_16816_PV_F16(vacc[2 * nbp + 1][0], vacc[2 * nbp + 1][1],
                             a[kc][0], a[kc][1], a[kc][2], a[kc][3], w2, w3);
        }
    }
    // q/k GEMMs
#pragma unroll
    for (int kc2 = 0; kc2 < 2; kc2++) {
        uint32_t chb = (uint32_t)((kc2 << 6) + ((mat >> 1) << 5) + ((mat & 1) << 4));
        uint32_t addr_off = (uint32_t)(j * 128) + (chb ^ xorj);
        uint32_t q0, q1, q2, q3;
        LDMATRIX_X4(q0, q1, q2, q3, sq + addr_off);
        MMA_16816_PV_F16(qacc[0], qacc[1],
                         a[2 * kc2][0], a[2 * kc2][1], a[2 * kc2][2], a[2 * kc2][3], q0, q1);
        MMA_16816_PV_F16(qacc[0], qacc[1],
                         a[2 * kc2 + 1][0], a[2 * kc2 + 1][1], a[2 * kc2 + 1][2], a[2 * kc2 + 1][3], q2, q3);
        uint32_t k0, k1, k2, k3;
        LDMATRIX_X4(k0, k1, k2, k3, sk + addr_off);
        MMA_16816_PV_F16(kacc[0], kacc[1],
                         a[2 * kc2][0], a[2 * kc2][1], a[2 * kc2][2], a[2 * kc2][3], k0, k1);
        MMA_16816_PV_F16(kacc[0], kacc[1],
                         a[2 * kc2 + 1][0], a[2 * kc2 + 1][1], a[2 * kc2 + 1][2], a[2 * kc2 + 1][3], k2, k3);
    }

    // epilogue: direct half2 stores in the attn-consumable layouts
    int pos0 = wm * 16 + r;
    int pos1 = pos0 + 8;
    size_t nidx0 = (size_t)b * NN + n0 + pos0;
    size_t nidx1 = (size_t)b * NN + n0 + pos1;
    int sw0 = (pos0 & 7) << 3, sw1 = (pos1 & 7) << 3;
    __half* vo0 = g_v + nidx0 * NC;
    __half* vo1 = g_v + nidx1 * NC;
#pragma unroll
    for (int nb = 0; nb < 8; nb++) {
        int ch = nb * 8 + 2 * cpr;
        *reinterpret_cast<uint32_t*>(vo0 + (ch ^ sw0)) = vacc[nb][0];
        *reinterpret_cast<uint32_t*>(vo1 + (ch ^ sw1)) = vacc[nb][1];
    }
    *reinterpret_cast<uint32_t*>(g_q + nidx0 * ND + 2 * cpr) = qacc[0];
    *reinterpret_cast<uint32_t*>(g_q + nidx1 * ND + 2 * cpr) = qacc[1];
    *reinterpret_cast<uint32_t*>(g_k + nidx0 * ND + 2 * cpr) = kacc[0];
    *reinterpret_cast<uint32_t*>(g_k + nidx1 * ND + 2 * cpr) = kacc[1];
}

// ============================================================================
// Kernel 1: projections, cp.async x staging (round 14, measured 11.6 us).
// ============================================================================
__global__ __launch_bounds__(THREADS) void proj_kernel(
    const float* __restrict__ x,
    const float* __restrict__ wq, const float* __restrict__ bq,
    const float* __restrict__ wk, const float* __restrict__ bk,
    const float* __restrict__ wv, const float* __restrict__ bv) {
    __shared__ __align__(16) float  s_xraw[64 * 64];   // 16KB raw fp32 x tile
    __shared__ __align__(16) __half s_x[64 * 64];      // 8KB swizzled fp16
    __shared__ __align__(16) __half s_wv[64 * 64];
    __shared__ __align__(16) __half s_wq[8 * 64];
    __shared__ __align__(16) __half s_wk[8 * 64];
    __shared__ float s_bv[64], s_bq[8], s_bk[8];

    int tid = threadIdx.x;
    int b = blockIdx.x >> 6;                 // 64 tiles of 64 pos per batch
    int n0 = (blockIdx.x & 63) * 64;
    char* sxc = reinterpret_cast<char*>(s_x);
    char* svc = reinterpret_cast<char*>(s_wv);
    char* sqc = reinterpret_cast<char*>(s_wq);
    char* skc = reinterpret_cast<char*>(s_wk);

    // ---- cp.async the raw x tile [64 ch x 64 pos] fp32 ----
    const float4* x4p = reinterpret_cast<const float4*>(x + (size_t)b * NC * NN + n0);
    uint32_t sxr = smem_u32(s_xraw);
    for (int t = tid; t < 1024; t += THREADS) {
        const float4* src = x4p + (size_t)(t >> 4) * (NN / 4) + (t & 15);
        CP_ASYNC16(sxr + (uint32_t)t * 16, src);
    }
    CP_COMMIT();

    // ---- stage W while the x tile is in flight ----
    const float4* wv4 = reinterpret_cast<const float4*>(wv);
    for (int t = tid; t < 1024; t += THREADS) {
        int r = t >> 4, c4 = t & 15;
        float4 w = wv4[t];
        uint32_t off = (uint32_t)(r * 128 + ((8 * c4) ^ ((r & 7) << 4)));
        *reinterpret_cast<__half2*>(svc + off)     = __floats2half2_rn(w.x, w.y);
        *reinterpret_cast<__half2*>(svc + off + 4) = __floats2half2_rn(w.z, w.w);
    }
    const float4* wq4 = reinterpret_cast<const float4*>(wq);
    const float4* wk4 = reinterpret_cast<const float4*>(wk);
    for (int t = tid; t < 128; t += THREADS) {
        int r = t >> 4, c4 = t & 15;
        uint32_t off = (uint32_t)(r * 128 + ((8 * c4) ^ ((r & 7) << 4)));
        float4 a = wq4[t];
        *reinterpret_cast<__half2*>(sqc + off)     = __floats2half2_rn(a.x * LOG2E, a.y * LOG2E);
        *reinterpret_cast<__half2*>(sqc + off + 4) = __floats2half2_rn(a.z * LOG2E, a.w * LOG2E);
        float4 k = wk4[t];
        *reinterpret_cast<__half2*>(skc + off)     = __floats2half2_rn(k.x, k.y);
        *reinterpret_cast<__half2*>(skc + off + 4) = __floats2half2_rn(k.z, k.w);
    }
    if (tid < 64) s_bv[tid] = bv[tid];
    if (tid < 8) { s_bq[tid] = bq[tid] * LOG2E; s_bk[tid] = bk[tid]; }

    // ---- convert own cp.async bytes -> swizzled fp16 (no sync needed) ----
    CP_WAIT(0);
    const float4* xr4 = reinterpret_cast<const float4*>(s_xraw);
    for (int t = tid; t < 1024; t += THREADS) {
        float4 w = xr4[t];
        int c = t >> 4, p4 = t & 15;
        uint32_t off = (uint32_t)(c * 128 + ((8 * p4) ^ ((c & 7) << 4)));
        *reinterpret_cast<__half2*>(sxc + off)     = __floats2half2_rn(w.x, w.y);
        *reinterpret_cast<__half2*>(sxc + off + 4) = __floats2half2_rn(w.z, w.w);
    }
    __syncthreads();

    proj_compute_tile(smem_u32(s_x), smem_u32(s_wv), smem_u32(s_wq),
                      smem_u32(s_wk), s_bv, s_bq, s_bk, b, n0, tid);
}

// ============================================================================
// Kernel 2: flash attention partial, SPLIT=2, TK=128 (round 13, measured
//   ~62 us; TK=64 experiment reverted).
// ============================================================================
__global__ __launch_bounds__(THREADS, 5) void attn_kernel() {
    __shared__ __align__(16) char smem[SM_BYTES];
    uint32_t sb = smem_u32(smem);

    int tid = threadIdx.x;
    int w = tid >> 5, l = tid & 31;
    int lr = l & 7, sub = l >> 3;
    int qr = w * 16;
    int b = blockIdx.y;
    int z = blockIdx.z;
    int i0 = blockIdx.x * TQ;
    int j_base = z * (NN / SPLIT);

    const uint4* gq4 = reinterpret_cast<const uint4*>(g_q) + (size_t)b * NN + i0;
    const uint4* gk4 = reinterpret_cast<const uint4*>(g_k) + (size_t)b * NN + j_base;
    const uint4* gv4 = reinterpret_cast<const uint4*>(g_v) + (size_t)b * NN * 8 + (size_t)j_base * 8;

    for (int t = tid; t < 64; t += THREADS)
        CP_ASYNC16(sb + SM_Q + (uint32_t)t * 16, gq4 + t);
    for (int t = tid; t < 128; t += THREADS)
        CP_ASYNC16(sb + SM_K0 + (uint32_t)t * 16, gk4 + t);
    for (int t = tid; t < 1024; t += THREADS)
        CP_ASYNC16(sb + SM_V0 + (uint32_t)t * 16, gv4 + t);
    CP_COMMIT();
    CP_WAIT(0);
    __syncthreads();

    uint32_t qaddr = sb + SM_Q + (uint32_t)(qr + (l & 15)) * 16;
    uint32_t koff = (uint32_t)(l & 15) * 16;
    uint32_t voff = (uint32_t)(lr + (sub & 1) * 8) * 128;
    uint32_t kb2[2] = { sb + SM_K0 + koff, sb + SM_K1 + koff };
    uint32_t vb2[2] = { sb + SM_V0 + voff, sb + SM_V1 + voff };
    int vsub = sub >> 1;

    uint32_t qa0, qa1;
    LDMATRIX_X2(qa0, qa1, qaddr);

    float o[32];
#pragma unroll
    for (int k = 0; k < 32; k++) o[k] = 0.f;
    float lsum0 = 0.f, lsum1 = 0.f;

    for (int t = 0; t < NT; t++) {
        if (t + 1 < NT) {
            uint32_t kd = (t & 1) ? SM_K0 : SM_K1;
            uint32_t vd = (t & 1) ? SM_V0 : SM_V1;
            const uint4* gk = gk4 + (t + 1) * 128;
            const uint4* gv = gv4 + (t + 1) * 1024;
            for (int u = tid; u < 128; u += THREADS)
                CP_ASYNC16(sb + kd + (uint32_t)u * 16, gk + u);
            for (int u = tid; u < 1024; u += THREADS)
                CP_ASYNC16(sb + vd + (uint32_t)u * 16, gv + u);
            CP_COMMIT();
        }
        if (t > 0) {
            if (t + 1 < NT) CP_WAIT(1); else CP_WAIT(0);
            __syncthreads();
        }

        uint32_t kbase = kb2[t & 1];
        uint32_t vbase = vb2[t & 1];
        uint32_t acc0 = 0, acc1 = 0;
        uint32_t o16[16];
#pragma unroll
        for (int k = 0; k < 16; k++) o16[k] = 0;

#pragma unroll
        for (int jt = 0; jt < 8; jt++) {
            uint32_t kr0, kr1;
            LDMATRIX_X2(kr0, kr1, kbase + (uint32_t)jt * 256);

            uint32_t pa0, pa1, pa2, pa3;
            MMA_K8_S_F16(pa0, pa1, qa0, qa1, kr0);
            MMA_K8_S_F16(pa2, pa3, qa0, qa1, kr1);

            EX2_F16X2(pa0, pa0);
            EX2_F16X2(pa1, pa1);
            EX2_F16X2(pa2, pa2);
            EX2_F16X2(pa3, pa3);
            uint32_t h0, h1;
            HADD2(h0, pa0, pa2); HADD2(acc0, acc0, h0);
            HADD2(h1, pa1, pa3); HADD2(acc1, acc1, h1);

            uint32_t vrow = vbase + (uint32_t)jt * 2048;
#pragma unroll
            for (int ct = 0; ct < 8; ct += 2) {
                uint32_t vr0, vr1, vr2, vr3;
                uint32_t va = vrow + (uint32_t)(((ct + vsub) ^ lr) << 4);
                LDMATRIX_X4_T(vr0, vr1, vr2, vr3, va);
                MMA_16816_PV_F16(o16[ct * 2 + 0], o16[ct * 2 + 1],
                                 pa0, pa1, pa2, pa3, vr0, vr1);
                MMA_16816_PV_F16(o16[ct * 2 + 2], o16[ct * 2 + 3],
                                 pa0, pa1, pa2, pa3, vr2, vr3);
            }
        }

#pragma unroll
        for (int ct = 0; ct < 8; ct++) {
            float2 f0 = __half22float2(*reinterpret_cast<__half2*>(&o16[ct * 2]));
            float2 f1 = __half22float2(*reinterpret_cast<__half2*>(&o16[ct * 2 + 1]));
            o[ct * 4 + 0] += f0.x;
            o[ct * 4 + 1] += f0.y;
            o[ct * 4 + 2] += f1.x;
            o[ct * 4 + 3] += f1.y;
        }
        {
            float2 f0 = __half22float2(*reinterpret_cast<__half2*>(&acc0));
            float2 f1 = __half22float2(*reinterpret_cast<__half2*>(&acc1));
            lsum0 += f0.x + f0.y;
            lsum1 += f1.x + f1.y;
        }
        __syncthreads();
    }

    lsum0 += __shfl_xor_sync(0xffffffffu, lsum0, 1);
    lsum0 += __shfl_xor_sync(0xffffffffu, lsum0, 2);
    lsum1 += __shfl_xor_sync(0xffffffffu, lsum1, 1);
    lsum1 += __shfl_xor_sync(0xffffffffu, lsum1, 2);
    float* lp = g_l[z] + (size_t)b * NN + i0;
    if ((l & 3) == 0) {
        lp[qr + (l >> 2)]     = lsum0;
        lp[qr + (l >> 2) + 8] = lsum1;
    }

    __syncthreads();
    float* so = reinterpret_cast<float*>(smem);
    int row0 = qr + (l >> 2);
    int cb = (l & 3) * 2;
#pragma unroll
    for (int ct = 0; ct < 8; ct++) {
        int c0 = ct * 8 + cb;
        so[c0 * 64 + row0]           = o[ct * 4 + 0];
        so[(c0 + 1) * 64 + row0]     = o[ct * 4 + 1];
        so[c0 * 64 + row0 + 8]       = o[ct * 4 + 2];
        so[(c0 + 1) * 64 + row0 + 8] = o[ct * 4 + 3];
    }
    __syncthreads();

    __half* gO = g_O[z] + (size_t)b * NC * NN + i0;
    const float4* so4 = reinterpret_cast<const float4*>(so);
    for (int t = tid; t < 1024; t += THREADS) {
        int c = t >> 4;
        int i = (t & 15) * 4;
        float4 v = so4[t];
        __half2 h0 = __floats2half2_rn(v.x, v.y);
        __half2 h1 = __floats2half2_rn(v.z, v.w);
        uint2 pk = make_uint2(*reinterpret_cast<uint32_t*>(&h0),
                              *reinterpret_cast<uint32_t*>(&h1));
        *reinterpret_cast<uint2*>(gO + (size_t)c * NN + i) = pk;
    }
}

// ============================================================================
// Kernel 3: combine split-K partials: out = gamma*(O0+O1)/(l0+l1) + x
// ============================================================================
__global__ __launch_bounds__(256) void combine_kernel(
    const float* __restrict__ x,
    const float* __restrict__ gamma,
    float* __restrict__ out) {
    int t = blockIdx.x * 256 + threadIdx.x;
    int b = t >> 16;
    int rem = t & 65535;
    int c = rem >> 10;
    int i = (rem & 1023) << 2;
    size_t oidx = ((size_t)b * NC + c) * NN + i;
    size_t lidx = (size_t)b * NN + i;

    const __half2* p0 = reinterpret_cast<const __half2*>(&g_O[0][oidx]);
    const __half2* p1 = reinterpret_cast<const __half2*>(&g_O[1][oidx]);
    float2 a0 = __half22float2(p0[0]), a1 = __half22float2(p0[1]);
    float2 b0 = __half22float2(p1[0]), b1 = __half22float2(p1[1]);
    float4 l0 = *reinterpret_cast<const float4*>(&g_l[0][lidx]);
    float4 l1 = *reinterpret_cast<const float4*>(&g_l[1][lidx]);
    float4 xr = *reinterpret_cast<const float4*>(&x[oidx]);
    float g = __ldg(gamma);

    float4 r;
    r.x = g * (a0.x + b0.x) / (l0.x + l1.x) + xr.x;
    r.y = g * (a0.y + b0.y) / (l0.y + l1.y) + xr.y;
    r.z = g * (a1.x + b1.x) / (l0.z + l1.z) + xr.z;
    r.w = g * (a1.y + b1.y) / (l0.w + l1.w) + xr.w;
    *reinterpret_cast<float4*>(&out[oidx]) = r;
}

extern "C" void kernel_launch(void* const* d_in, const int* in_sizes, int n_in,
                              void* d_out, int out_size) {
    const float* x     = (const float*)d_in[0];
    const float* wq    = (const float*)d_in[1];
    const float* bq    = (const float*)d_in[2];
    const float* wk    = (const float*)d_in[3];
    const float* bk    = (const float*)d_in[4];
    const float* wv    = (const float*)d_in[5];
    const float* bv    = (const float*)d_in[6];
    const float* gamma = (const float*)d_in[7];
    float* out = (float*)d_out;

    proj_kernel<<<NB * NN / 64, THREADS>>>(x, wq, bq, wk, bk, wv, bv);
    attn_kernel<<<dim3(NN / TQ, NB, SPLIT), THREADS>>>();
    combine_kernel<<<NB * NC * NN / 4 / 256, 256>>>(x, gamma, out);
}